// round 16
// baseline (speedup 1.0000x reference)
#include <cuda_runtime.h>
#include <cuda_bf16.h>
#include <cstddef>

#define NUM_CLASS 1000
#define DIMS      2048
#define HEADSZ    256
#define NSAMP     16384
#define ALPHA_F   0.999f
#define BETA_F    (1.0f - ALPHA_F)

#define GRID_B 888                 // 148 SMs x 6 CTAs: one wave at occ 6
#define CHUNK 2048                 // labels per backward-scan chunk
#define NCHUNK (NSAMP / CHUNK)     // 8

// Scratch: only the loss accumulator + ticket remain (self-resetting).
__device__ double g_loss_accum;
__device__ int    g_ticket;

// ---------------------------------------------------------------------------
// Single kernel, zero cross-CTA synchronization (R15 skeleton):
//   phase 1: loss stream at SAMPLE granularity -- x double-buffered one
//            sample ahead (16 regs), centers JIT. launch_bounds(256,6)
//            -> ~40 regs -> 6 CTAs/SM (occ ~72%): the JIT center-load
//            latency is covered by warps instead of registers.
//   phase 2: per-CTA EMA update; each CTA finds its classes' last occurrence
//            itself via backward early-exit label scan (L2-hot).
//   phase 3: block reduce + one atomic per CTA; last CTA finalizes + resets.
// ---------------------------------------------------------------------------
__global__ __launch_bounds__(256, 6) void ema_fused_kernel(
    const float* __restrict__ x,
    const int*   __restrict__ labels,
    const float* __restrict__ centers,
    float*       __restrict__ out_loss,      // may be null
    float*       __restrict__ out_centers)
{
    const int t   = threadIdx.x;
    const int G   = gridDim.x;
    const int bid = blockIdx.x;

    // ---- phase 1: loss stream, 1 sample/iter, x-only double buffer ----
    const int cnt = (NSAMP - bid + G - 1) / G;   // samples for this CTA

#define NS(i) (bid + (i) * G)

#define LOADX(buf, n)                                                            \
    do {                                                                         \
        const float4* __restrict__ xr =                                          \
            reinterpret_cast<const float4*>(x + (size_t)(n) * DIMS);             \
        buf[0] = __ldcs(&xr[t]);                                                 \
        buf[1] = __ldcs(&xr[t + 256]);                                           \
    } while (0)

    // Consume one sample: JIT center loads (covered by occupancy), 4 accums.
#define CONSUME(xb, lab)                                                         \
    do {                                                                         \
        const float4* __restrict__ cr =                                          \
            reinterpret_cast<const float4*>(centers + (size_t)(lab) * DIMS);     \
        const float4 c0 = cr[t];                                                 \
        const float4 c1 = cr[t + 256];                                           \
        float d;                                                                 \
        s0 += (d = xb[0].x - c0.x) * d;                                          \
        s1 += (d = xb[0].y - c0.y) * d;                                          \
        s2 += (d = xb[0].z - c0.z) * d;                                          \
        s3 += (d = xb[0].w - c0.w) * d;                                          \
        s0 += (d = xb[1].x - c1.x) * d;                                          \
        s1 += (d = xb[1].y - c1.y) * d;                                          \
        s2 += (d = xb[1].z - c1.z) * d;                                          \
        s3 += (d = xb[1].w - c1.w) * d;                                          \
    } while (0)

    float4 Xa[2], Xb[2];
    float s0 = 0.0f, s1 = 0.0f, s2 = 0.0f, s3 = 0.0f;
    int labA = 0, labB = 0;

    if (0 < cnt) { LOADX(Xa, NS(0)); labA = labels[NS(0)]; }
    if (1 < cnt) { LOADX(Xb, NS(1)); labB = labels[NS(1)]; }

    for (int i = 0; i < cnt; i += 2) {
        // slot A: sample i (x loads issued one iteration ago)
        CONSUME(Xa, labA);
        if (i + 2 < cnt) { LOADX(Xa, NS(i + 2)); labA = labels[NS(i + 2)]; }

        if (i + 1 >= cnt) break;
        // slot B: sample i+1
        CONSUME(Xb, labB);
        if (i + 3 < cnt) { LOADX(Xb, NS(i + 3)); labB = labels[NS(i + 3)]; }
    }
#undef NS
#undef LOADX
#undef CONSUME

    float s = (s0 + s1) + (s2 + s3);

    // ---- phase 2: self-contained EMA update for this CTA's classes ----
    __shared__ int sh_last;

    for (int c = bid; c < NUM_CLASS; c += G) {
        // Backward early-exit scan: first (from the back) chunk containing
        // class c yields the global last occurrence.
        int last = -1;
        for (int chunk = NCHUNK - 1; chunk >= 0; --chunk) {
            if (t == 0) sh_last = -1;
            __syncthreads();

            const int nbase = chunk * CHUNK + t * 8;
            const int4* __restrict__ lq =
                reinterpret_cast<const int4*>(labels + nbase);
            const int4 a = lq[0];
            const int4 bb = lq[1];
            int mymax = -1;
            if (a.x  == c) mymax = nbase + 0;
            if (a.y  == c) mymax = nbase + 1;
            if (a.z  == c) mymax = nbase + 2;
            if (a.w  == c) mymax = nbase + 3;
            if (bb.x == c) mymax = nbase + 4;
            if (bb.y == c) mymax = nbase + 5;
            if (bb.z == c) mymax = nbase + 6;
            if (bb.w == c) mymax = nbase + 7;
            if (mymax >= 0) atomicMax(&sh_last, mymax);
            __syncthreads();

            if (sh_last >= 0) { last = sh_last; break; }
        }

        const float4* __restrict__ cr =
            reinterpret_cast<const float4*>(centers + (size_t)c * DIMS);
        float* __restrict__ oc = out_centers + (size_t)c * DIMS;

        if (last >= 0) {
            const float4* __restrict__ xr =
                reinterpret_cast<const float4*>(x + (size_t)last * DIMS);
            const float4 cv0 = cr[t];
            const float4 cv1 = cr[t + 256];
            const float4 xv0 = __ldcs(&xr[t]);
            const float4 xv1 = __ldcs(&xr[t + 256]);
            const int ob = t * 4;
            __stcs(&oc[ob + 0], ALPHA_F * cv0.x + BETA_F * xv0.x);
            __stcs(&oc[ob + 1], ALPHA_F * cv0.y + BETA_F * xv0.y);
            __stcs(&oc[ob + 2], ALPHA_F * cv0.z + BETA_F * xv0.z);
            __stcs(&oc[ob + 3], ALPHA_F * cv0.w + BETA_F * xv0.w);
            __stcs(&oc[ob + 1024], ALPHA_F * cv1.x + BETA_F * xv1.x);
            __stcs(&oc[ob + 1025], ALPHA_F * cv1.y + BETA_F * xv1.y);
            __stcs(&oc[ob + 1026], ALPHA_F * cv1.z + BETA_F * xv1.z);
            __stcs(&oc[ob + 1027], ALPHA_F * cv1.w + BETA_F * xv1.w);
        } else {
            const float4 cv0 = cr[t];
            const float4 cv1 = cr[t + 256];
            const int ob = t * 4;
            __stcs(&oc[ob + 0], cv0.x);
            __stcs(&oc[ob + 1], cv0.y);
            __stcs(&oc[ob + 2], cv0.z);
            __stcs(&oc[ob + 3], cv0.w);
            __stcs(&oc[ob + 1024], cv1.x);
            __stcs(&oc[ob + 1025], cv1.y);
            __stcs(&oc[ob + 1026], cv1.z);
            __stcs(&oc[ob + 1027], cv1.w);
        }
        __syncthreads();   // sh_last reuse across classes
    }

    // ---- phase 3: block reduce + single atomic per CTA ----
#pragma unroll
    for (int o = 16; o > 0; o >>= 1) s += __shfl_xor_sync(0xFFFFFFFFu, s, o);

    __shared__ float warp_s[8];
    if ((t & 31) == 0) warp_s[t >> 5] = s;
    __syncthreads();

    if (t == 0) {
        float v = warp_s[0] + warp_s[1] + warp_s[2] + warp_s[3]
                + warp_s[4] + warp_s[5] + warp_s[6] + warp_s[7];
        atomicAdd(&g_loss_accum, (double)v);
        __threadfence();
        const int old = atomicAdd(&g_ticket, 1);
        if (old == G - 1) {
            if (out_loss != nullptr) {
                *out_loss = (float)(g_loss_accum / ((double)NSAMP * (double)HEADSZ));
            }
            g_loss_accum = 0.0;
            g_ticket     = 0;
        }
    }
}

// ---------------------------------------------------------------------------
extern "C" void kernel_launch(void* const* d_in, const int* in_sizes, int n_in,
                              void* d_out, int out_size) {
    const float* x       = (const float*)d_in[0];
    const int*   labels  = (const int*)  d_in[1];
    const float* centers = (const float*)d_in[2];

    float* out = (float*)d_out;
    const int centers_elems = NUM_CLASS * DIMS;          // 2,048,000
    float* out_centers = out + (out_size - centers_elems);
    float* out_loss    = (out_size > centers_elems) ? out : nullptr;

    ema_fused_kernel<<<GRID_B, 256>>>(x, labels, centers,
                                      out_loss, out_centers);
}

// round 17
// speedup vs baseline: 1.0707x; 1.0707x over previous
#include <cuda_runtime.h>
#include <cuda_bf16.h>
#include <cstddef>
#include <cstdint>

#define NUM_CLASS 1000
#define DIMS      2048
#define HEADSZ    256
#define NSAMP     16384
#define ALPHA_F   0.999f
#define BETA_F    (1.0f - ALPHA_F)

#define TOTAL_PAIRS (NSAMP / 2)    // 8192
#define GRID_B 608
#define CHUNK 2048                 // labels per backward-scan chunk
#define NCHUNK (NSAMP / CHUNK)     // 8

// Scratch: only the loss accumulator + ticket remain (self-resetting).
__device__ double g_loss_accum;
__device__ int    g_ticket;

// ---------------------------------------------------------------------------
// Single kernel, zero cross-CTA synchronization (R15 skeleton, tail shrunk):
//   phase 0: per-CTA backward label scan for this CTA's 1-2 classes (labels
//            are an input -- no dependency). Winner x-rows + center rows are
//            L2-prefetched here, 25us before use.
//   phase 1: loss stream -- pair-granularity x-register double buffer + 4
//            independent accumulators (the proven best flow, untouched).
//   phase 2: EMA update: now an L2-hit gather + (vectorized when aligned)
//            stores. The cold-DRAM dependent tail is gone.
//   phase 3: block reduce + one atomic per CTA; last CTA finalizes + resets.
// ---------------------------------------------------------------------------
__global__ __launch_bounds__(256, 4) void ema_fused_kernel(
    const float* __restrict__ x,
    const int*   __restrict__ labels,
    const float* __restrict__ centers,
    float*       __restrict__ out_loss,      // may be null
    float*       __restrict__ out_centers)
{
    const int t   = threadIdx.x;
    const int G   = gridDim.x;
    const int bid = blockIdx.x;
    const int2* __restrict__ lp = reinterpret_cast<const int2*>(labels);

    // ---- phase 0: backward early-exit scans + L2 prefetch ----
    __shared__ int sh_last;
    const int ncls = (bid + G < NUM_CLASS) ? 2 : 1;   // bid < 608 <= NUM_CLASS
    int lastv[2] = {-1, -1};

#pragma unroll
    for (int k = 0; k < 2; ++k) {
        if (k >= ncls) break;
        const int c = bid + k * G;
        for (int chunk = NCHUNK - 1; chunk >= 0; --chunk) {
            if (t == 0) sh_last = -1;
            __syncthreads();

            const int nbase = chunk * CHUNK + t * 8;
            const int4* __restrict__ lq =
                reinterpret_cast<const int4*>(labels + nbase);
            const int4 a  = lq[0];
            const int4 bb = lq[1];
            int mymax = -1;
            if (a.x  == c) mymax = nbase + 0;
            if (a.y  == c) mymax = nbase + 1;
            if (a.z  == c) mymax = nbase + 2;
            if (a.w  == c) mymax = nbase + 3;
            if (bb.x == c) mymax = nbase + 4;
            if (bb.y == c) mymax = nbase + 5;
            if (bb.z == c) mymax = nbase + 6;
            if (bb.w == c) mymax = nbase + 7;
            if (mymax >= 0) atomicMax(&sh_last, mymax);
            __syncthreads();

            if (sh_last >= 0) { lastv[k] = sh_last; break; }
        }
        // Prefetch the winner x row (8 KB = 64 lines) and center row into L2.
        if (lastv[k] >= 0 && t < 64) {
            const float* xr = x + (size_t)lastv[k] * DIMS + t * 32;
            asm volatile("prefetch.global.L2 [%0];" :: "l"(xr));
            const float* cc = centers + (size_t)c * DIMS + t * 32;
            asm volatile("prefetch.global.L2 [%0];" :: "l"(cc));
        }
        __syncthreads();
    }

    // ---- phase 1: loss stream (untouched R10/R15 flow) ----
    float4 b0[4], b1[4];
    int p0 = bid;
    int p1 = bid + G;
    int2 L0, L1;

#define LOAD_PAIR(buf, p)                                                        \
    do {                                                                         \
        const float4* __restrict__ xr0 =                                         \
            reinterpret_cast<const float4*>(x + (size_t)(2 * (p)) * DIMS);       \
        const float4* __restrict__ xr1 =                                         \
            reinterpret_cast<const float4*>(x + (size_t)(2 * (p) + 1) * DIMS);   \
        buf[0] = __ldcs(&xr0[t]);                                                \
        buf[1] = __ldcs(&xr0[t + 256]);                                          \
        buf[2] = __ldcs(&xr1[t]);                                                \
        buf[3] = __ldcs(&xr1[t + 256]);                                          \
    } while (0)

#define SQD(acc, a, b)                                                           \
    do {                                                                         \
        float d;                                                                 \
        acc += (d = (a).x - (b).x) * d;                                          \
        acc += (d = (a).y - (b).y) * d;                                          \
        acc += (d = (a).z - (b).z) * d;                                          \
        acc += (d = (a).w - (b).w) * d;                                          \
    } while (0)

#define CONSUME(buf, L)                                                          \
    do {                                                                         \
        const float4* __restrict__ cr0 =                                         \
            reinterpret_cast<const float4*>(centers + (size_t)(L).x * DIMS);     \
        const float4* __restrict__ cr1 =                                         \
            reinterpret_cast<const float4*>(centers + (size_t)(L).y * DIMS);     \
        const float4 c0 = cr0[t];                                                \
        const float4 c1 = cr0[t + 256];                                          \
        const float4 c2 = cr1[t];                                                \
        const float4 c3 = cr1[t + 256];                                          \
        SQD(s0, buf[0], c0);                                                     \
        SQD(s1, buf[1], c1);                                                     \
        SQD(s2, buf[2], c2);                                                     \
        SQD(s3, buf[3], c3);                                                     \
    } while (0)

    float s0 = 0.0f, s1 = 0.0f, s2 = 0.0f, s3 = 0.0f;
    if (p0 < TOTAL_PAIRS) { LOAD_PAIR(b0, p0); L0 = lp[p0]; }
    if (p1 < TOTAL_PAIRS) { LOAD_PAIR(b1, p1); L1 = lp[p1]; }

    while (p0 < TOTAL_PAIRS) {
        CONSUME(b0, L0);
        p0 += 2 * G;
        if (p0 < TOTAL_PAIRS) { LOAD_PAIR(b0, p0); L0 = lp[p0]; }

        if (p1 >= TOTAL_PAIRS) break;
        CONSUME(b1, L1);
        p1 += 2 * G;
        if (p1 < TOTAL_PAIRS) { LOAD_PAIR(b1, p1); L1 = lp[p1]; }
    }
#undef LOAD_PAIR
#undef SQD
#undef CONSUME

    float s = (s0 + s1) + (s2 + s3);

    // ---- phase 2: EMA update (L2-hot gather; vectorized stores if aligned) ----
    const bool aligned16 = (((uintptr_t)out_centers) & 15u) == 0;

#pragma unroll
    for (int k = 0; k < 2; ++k) {
        if (k >= ncls) break;
        const int c    = bid + k * G;
        const int last = lastv[k];

        const float4* __restrict__ cr =
            reinterpret_cast<const float4*>(centers + (size_t)c * DIMS);
        float* __restrict__ oc = out_centers + (size_t)c * DIMS;

        float4 r0, r1;
        if (last >= 0) {
            const float4* __restrict__ xr =
                reinterpret_cast<const float4*>(x + (size_t)last * DIMS);
            const float4 cv0 = cr[t];
            const float4 cv1 = cr[t + 256];
            const float4 xv0 = xr[t];
            const float4 xv1 = xr[t + 256];
            r0.x = ALPHA_F * cv0.x + BETA_F * xv0.x;
            r0.y = ALPHA_F * cv0.y + BETA_F * xv0.y;
            r0.z = ALPHA_F * cv0.z + BETA_F * xv0.z;
            r0.w = ALPHA_F * cv0.w + BETA_F * xv0.w;
            r1.x = ALPHA_F * cv1.x + BETA_F * xv1.x;
            r1.y = ALPHA_F * cv1.y + BETA_F * xv1.y;
            r1.z = ALPHA_F * cv1.z + BETA_F * xv1.z;
            r1.w = ALPHA_F * cv1.w + BETA_F * xv1.w;
        } else {
            r0 = cr[t];
            r1 = cr[t + 256];
        }

        if (aligned16) {
            float4* __restrict__ ov = reinterpret_cast<float4*>(oc);
            __stcs(&ov[t], r0);
            __stcs(&ov[t + 256], r1);
        } else {
            const int ob = t * 4;
            __stcs(&oc[ob + 0], r0.x);
            __stcs(&oc[ob + 1], r0.y);
            __stcs(&oc[ob + 2], r0.z);
            __stcs(&oc[ob + 3], r0.w);
            __stcs(&oc[ob + 1024], r1.x);
            __stcs(&oc[ob + 1025], r1.y);
            __stcs(&oc[ob + 1026], r1.z);
            __stcs(&oc[ob + 1027], r1.w);
        }
    }

    // ---- phase 3: block reduce + single atomic per CTA ----
#pragma unroll
    for (int o = 16; o > 0; o >>= 1) s += __shfl_xor_sync(0xFFFFFFFFu, s, o);

    __shared__ float warp_s[8];
    if ((t & 31) == 0) warp_s[t >> 5] = s;
    __syncthreads();

    if (t == 0) {
        float v = warp_s[0] + warp_s[1] + warp_s[2] + warp_s[3]
                + warp_s[4] + warp_s[5] + warp_s[6] + warp_s[7];
        atomicAdd(&g_loss_accum, (double)v);
        __threadfence();
        const int old = atomicAdd(&g_ticket, 1);
        if (old == G - 1) {
            if (out_loss != nullptr) {
                *out_loss = (float)(g_loss_accum / ((double)NSAMP * (double)HEADSZ));
            }
            g_loss_accum = 0.0;
            g_ticket     = 0;
        }
    }
}

// ---------------------------------------------------------------------------
extern "C" void kernel_launch(void* const* d_in, const int* in_sizes, int n_in,
                              void* d_out, int out_size) {
    const float* x       = (const float*)d_in[0];
    const int*   labels  = (const int*)  d_in[1];
    const float* centers = (const float*)d_in[2];

    float* out = (float*)d_out;
    const int centers_elems = NUM_CLASS * DIMS;          // 2,048,000
    float* out_centers = out + (out_size - centers_elems);
    float* out_loss    = (out_size > centers_elems) ? out : nullptr;

    ema_fused_kernel<<<GRID_B, 256>>>(x, labels, centers,
                                      out_loss, out_centers);
}